// round 14
// baseline (speedup 1.0000x reference)
#include <cuda_runtime.h>
#include <cuda_bf16.h>
#include <cstdint>

// LIF spiking scan:  x[B,S,H] -> spikes[B,S,H]   (B=8, S=2048, H=4096, fp32)
//   mem = decay*mem + x_t ; ref = max(ref-1,0)
//   spk = (ref==0 && mem>thr) ; mem *= (1-spk) ; ref += 5*spk
//
// R12 (float4, 256x32, 6-stage cp.async loads, STG.128 stores) = 95.0us
// (ncu 83.6, DRAM 71.5%). R13 showed narrower accesses + more warps regress:
// the binding resource is the per-SM LSU/L1tex path, and 16x STG.128 per
// chunk-warp (192 of 384 LSU cyc) is the biggest item. R14: identical load
// pipeline, but stores go SMEM-staged (16x STS.128, smem port) and are
// drained by lane0 via 16x cp.async.bulk 1D shared->global row copies
// (512B each) on the bulk/TMA engine -- off the LSU and out of the L1tex
// wavefront queue. Double-buffered staging, bulk-group accounting (separate
// counter from cp.async groups). 64KB dynamic smem.

#define LIF_B 8
#define LIF_S 2048
#define LIF_H 4096

static constexpr int U = 16;               // timesteps per stage
static constexpr int STAGES = 6;           // load stages: 6*16*128*4B = 48KB
static constexpr int NCHUNK = LIF_S / U;   // 128
static constexpr float REFRACTORY = 5.0f;

static constexpr int LOAD_FLOATS  = STAGES * U * 128;   // 12288 floats
static constexpr int STBUF_FLOATS = U * 128;            // 2048 floats per buf
static constexpr int SMEM_BYTES   = (LOAD_FLOATS + 2 * STBUF_FLOATS) * 4; // 64KB

__global__ __launch_bounds__(32, 2)
void lif_scan_v4_bulk(const float* __restrict__ x,
                      const float* __restrict__ thr_p,
                      const float* __restrict__ dec_p,
                      float* __restrict__ out)
{
    extern __shared__ float smem[];   // [0,12288) load stages; [12288,+2x2048) store bufs

    const int lane = threadIdx.x;            // 0..31
    const int n0   = blockIdx.x * 128;       // first neuron of this block
    const int b     = n0 >> 12;              // n0 / H
    const int hbase = n0 & (LIF_H - 1);      // n0 % H

    const float thr   = __ldg(thr_p);
    const float decay = __ldg(dec_p);

    const float* __restrict__ xbase = x + b * (LIF_S * LIF_H) + hbase;
    float* __restrict__ obase = out + b * (LIF_S * LIF_H) + hbase;  // row t: +t*H

    // ---- load pipeline (identical to R12) ----
    // tile row = 128 floats = 512B = one warp-wide cp.async op (16B/lane).
    const float* __restrict__ wsrc = xbase + lane * 4;
    const unsigned smem_ld0 =
        (unsigned)__cvta_generic_to_shared(&smem[lane * 4]);

    auto issue_chunk = [&](int c) {
        const unsigned sbase = smem_ld0 + (unsigned)(c % STAGES) * (U * 512u);
        const float* src = wsrc + (c * U) * LIF_H;
        #pragma unroll
        for (int j = 0; j < U; ++j) {
            asm volatile("cp.async.cg.shared.global [%0], [%1], 16;\n"
                         :: "r"(sbase + (unsigned)j * 512u),
                            "l"(src + j * LIF_H));
        }
    };

    #pragma unroll
    for (int c = 0; c < STAGES - 2; ++c) {
        issue_chunk(c);
        asm volatile("cp.async.commit_group;\n" ::: "memory");
    }

    // ---- store staging ----
    float* stbuf[2] = { smem + LOAD_FLOATS, smem + LOAD_FLOATS + STBUF_FLOATS };
    const unsigned stsm[2] = {
        (unsigned)__cvta_generic_to_shared(stbuf[0]),
        (unsigned)__cvta_generic_to_shared(stbuf[1])
    };

    float mem0 = 0.f, mem1 = 0.f, mem2 = 0.f, mem3 = 0.f;
    float ref0 = 0.f, ref1 = 0.f, ref2 = 0.f, ref3 = 0.f;

    for (int c = 0; c < NCHUNK; ++c) {
        if (c + STAGES - 2 < NCHUNK)
            issue_chunk(c + STAGES - 2);
        asm volatile("cp.async.commit_group;\n" ::: "memory");
        asm volatile("cp.async.wait_group %0;\n" :: "n"(STAGES - 2) : "memory");

        // Reuse guard for store buffer c&1: allow <=1 bulk group in flight,
        // so the group from chunk c-2 (this buffer) has finished reading smem.
        if (lane == 0)
            asm volatile("cp.async.bulk.wait_group.read 1;\n" ::: "memory");
        __syncwarp();   // also covers load-stage producer==consumer ordering

        const int s  = c % STAGES;
        float* sb    = stbuf[c & 1];

        float4 v[U];
        #pragma unroll
        for (int i = 0; i < U; ++i)
            v[i] = *reinterpret_cast<const float4*>(&smem[s * (U * 128) + i * 128 + lane * 4]);

        #pragma unroll
        for (int i = 0; i < U; ++i) {
            float4 spk;

            mem0 = fmaf(decay, mem0, v[i].x);
            ref0 = fmaxf(ref0 - 1.0f, 0.0f);
            {
                const bool sp = (ref0 == 0.0f) && (mem0 > thr);
                spk.x = sp ? 1.0f : 0.0f;
                mem0  = sp ? 0.0f : mem0;
                ref0  = sp ? REFRACTORY : ref0;   // spike implies ref was 0
            }
            mem1 = fmaf(decay, mem1, v[i].y);
            ref1 = fmaxf(ref1 - 1.0f, 0.0f);
            {
                const bool sp = (ref1 == 0.0f) && (mem1 > thr);
                spk.y = sp ? 1.0f : 0.0f;
                mem1  = sp ? 0.0f : mem1;
                ref1  = sp ? REFRACTORY : ref1;
            }
            mem2 = fmaf(decay, mem2, v[i].z);
            ref2 = fmaxf(ref2 - 1.0f, 0.0f);
            {
                const bool sp = (ref2 == 0.0f) && (mem2 > thr);
                spk.z = sp ? 1.0f : 0.0f;
                mem2  = sp ? 0.0f : mem2;
                ref2  = sp ? REFRACTORY : ref2;
            }
            mem3 = fmaf(decay, mem3, v[i].w);
            ref3 = fmaxf(ref3 - 1.0f, 0.0f);
            {
                const bool sp = (ref3 == 0.0f) && (mem3 > thr);
                spk.w = sp ? 1.0f : 0.0f;
                mem3  = sp ? 0.0f : mem3;
                ref3  = sp ? REFRACTORY : ref3;
            }

            *reinterpret_cast<float4*>(&sb[i * 128 + lane * 4]) = spk;  // STS.128
        }

        // Drain staged tile: 16 x 512B bulk row copies on the bulk engine.
        __syncwarp();   // all lanes' STS visible (generic proxy)
        if (lane == 0) {
            asm volatile("fence.proxy.async.shared::cta;\n" ::: "memory");
            float* grow = obase + (c * U) * LIF_H;
            const unsigned sb32 = stsm[c & 1];
            #pragma unroll
            for (int i = 0; i < U; ++i) {
                asm volatile("cp.async.bulk.global.shared::cta.bulk_group [%0], [%1], 512;\n"
                             :: "l"(grow + i * LIF_H), "r"(sb32 + (unsigned)i * 512u)
                             : "memory");
            }
            asm volatile("cp.async.bulk.commit_group;\n" ::: "memory");
        }
    }

    // Ensure all bulk stores are globally visible before kernel exit.
    if (lane == 0)
        asm volatile("cp.async.bulk.wait_group 0;\n" ::: "memory");
}

extern "C" void kernel_launch(void* const* d_in, const int* in_sizes, int n_in,
                              void* d_out, int out_size)
{
    // metadata order: x [B,S,H] f32, membrane_threshold f32, decay_rate f32
    const float* x     = (const float*)d_in[0];
    const float* thr_p = (const float*)d_in[1];
    const float* dec_p = (const float*)d_in[2];
    float* out = (float*)d_out;

    cudaFuncSetAttribute(lif_scan_v4_bulk,
                         cudaFuncAttributeMaxDynamicSharedMemorySize, SMEM_BYTES);

    const int blocks = (LIF_B * LIF_H) / 128;   // 256 blocks, exact cover

    lif_scan_v4_bulk<<<blocks, 32, SMEM_BYTES>>>(x, thr_p, dec_p, out);
}

// round 15
// speedup vs baseline: 1.3925x; 1.3925x over previous
#include <cuda_runtime.h>
#include <cuda_bf16.h>
#include <cstdint>

// LIF spiking scan:  x[B,S,H] -> spikes[B,S,H]   (B=8, S=2048, H=4096, fp32)
//   mem = decay*mem + x_t ; ref = max(ref-1,0)
//   spk = (ref==0 && mem>thr) ; mem *= (1-spk) ; ref += 5*spk
//
// Best = R12 (float4 lanes, 256x32, cp.async pipeline, STG.128): 95.0us,
// ncu 83.6, DRAM 71.5%, issue 54.5% @ 1.73 warps/SM -> per-warp instruction
// stream is a co-limiter (~44us issue floor of 84us total). R15:
//  (a) recurrence re-encoded with next-eligible-time integer `na`:
//      sp = (i >= na) && (mem > thr); na = sp ? i+5 : na; na -= U per chunk.
//      (spike at t -> ref=5 -> eligible again exactly at t+5). Cuts ~9 ->
//      ~6 instrs per neuron-step, stream -30%.
//  (b) STAGES 6 -> 10 (80KB dynamic smem/block, 2 blocks/SM = 160KB):
//      deeper in-flight absorbs DRAM latency jitter.
// Load/store structure identical to R12 (distributed STG.128 -- R14 proved
// serialized bulk stores regress badly).

#define LIF_B 8
#define LIF_S 2048
#define LIF_H 4096

static constexpr int U = 16;                // timesteps per stage
static constexpr int STAGES = 10;           // 10 * 16*128*4B = 80KB dynamic smem
static constexpr int NCHUNK = LIF_S / U;    // 128
static constexpr int SMEM_BYTES = STAGES * U * 128 * 4;

__global__ __launch_bounds__(32, 2)
void lif_scan_v4b(const float* __restrict__ x,
                  const float* __restrict__ thr_p,
                  const float* __restrict__ dec_p,
                  float* __restrict__ out)
{
    extern __shared__ float smem[];          // [STAGES][U][128]

    const int lane = threadIdx.x;            // 0..31
    const int n0   = blockIdx.x * 128;       // first neuron of this block
    const int b     = n0 >> 12;              // n0 / H
    const int hbase = n0 & (LIF_H - 1);      // n0 % H

    const float thr   = __ldg(thr_p);
    const float decay = __ldg(dec_p);

    const float* __restrict__ xbase = x   + b * (LIF_S * LIF_H) + hbase;
    float* __restrict__       obase = out + b * (LIF_S * LIF_H) + hbase + lane * 4;

    // tile row = 128 floats = 512B = one warp-wide cp.async op (16B/lane).
    const float* __restrict__ wsrc = xbase + lane * 4;
    const unsigned smem0 =
        (unsigned)__cvta_generic_to_shared(&smem[lane * 4]);

    auto issue_chunk = [&](int c) {
        const unsigned sbase = smem0 + (unsigned)(c % STAGES) * (U * 512u);
        const float* src = wsrc + (c * U) * LIF_H;
        #pragma unroll
        for (int j = 0; j < U; ++j) {
            asm volatile("cp.async.cg.shared.global [%0], [%1], 16;\n"
                         :: "r"(sbase + (unsigned)j * 512u),
                            "l"(src + j * LIF_H));
        }
    };

    // Prologue: fill STAGES-2 stages, one commit group each.
    #pragma unroll
    for (int c = 0; c < STAGES - 2; ++c) {
        issue_chunk(c);
        asm volatile("cp.async.commit_group;\n" ::: "memory");
    }

    // 4 independent neuron states: membrane + next-eligible step (chunk-rel).
    float mem0 = 0.f, mem1 = 0.f, mem2 = 0.f, mem3 = 0.f;
    int   na0 = 0, na1 = 0, na2 = 0, na3 = 0;   // eligible when i >= na

    for (int c = 0; c < NCHUNK; ++c) {
        if (c + STAGES - 2 < NCHUNK)
            issue_chunk(c + STAGES - 2);
        // Always commit (empty tail groups keep wait_group<STAGES-2> aligned
        // so chunk c's group is guaranteed complete below).
        asm volatile("cp.async.commit_group;\n" ::: "memory");
        asm volatile("cp.async.wait_group %0;\n" :: "n"(STAGES - 2) : "memory");
        __syncwarp();   // single-warp block: producer == consumer warp

        const int s = c % STAGES;

        float4 v[U];
        #pragma unroll
        for (int i = 0; i < U; ++i)
            v[i] = *reinterpret_cast<const float4*>(&smem[s * (U * 128) + i * 128 + lane * 4]);

        float* __restrict__ o = obase + (c * U) * LIF_H;
        #pragma unroll
        for (int i = 0; i < U; ++i) {
            float4 spk;

            mem0 = fmaf(decay, mem0, v[i].x);
            {
                const bool sp = (i >= na0) & (mem0 > thr);
                spk.x = sp ? 1.0f : 0.0f;
                mem0  = sp ? 0.0f : mem0;
                na0   = sp ? (i + 5) : na0;
            }
            mem1 = fmaf(decay, mem1, v[i].y);
            {
                const bool sp = (i >= na1) & (mem1 > thr);
                spk.y = sp ? 1.0f : 0.0f;
                mem1  = sp ? 0.0f : mem1;
                na1   = sp ? (i + 5) : na1;
            }
            mem2 = fmaf(decay, mem2, v[i].z);
            {
                const bool sp = (i >= na2) & (mem2 > thr);
                spk.z = sp ? 1.0f : 0.0f;
                mem2  = sp ? 0.0f : mem2;
                na2   = sp ? (i + 5) : na2;
            }
            mem3 = fmaf(decay, mem3, v[i].w);
            {
                const bool sp = (i >= na3) & (mem3 > thr);
                spk.w = sp ? 1.0f : 0.0f;
                mem3  = sp ? 0.0f : mem3;
                na3   = sp ? (i + 5) : na3;
            }

            *reinterpret_cast<float4*>(&o[i * LIF_H]) = spk;   // STG.128
        }

        // Shift next-eligible times into next chunk's local frame.
        na0 -= U; na1 -= U; na2 -= U; na3 -= U;
    }
}

extern "C" void kernel_launch(void* const* d_in, const int* in_sizes, int n_in,
                              void* d_out, int out_size)
{
    // metadata order: x [B,S,H] f32, membrane_threshold f32, decay_rate f32
    const float* x     = (const float*)d_in[0];
    const float* thr_p = (const float*)d_in[1];
    const float* dec_p = (const float*)d_in[2];
    float* out = (float*)d_out;

    cudaFuncSetAttribute(lif_scan_v4b,
                         cudaFuncAttributeMaxDynamicSharedMemorySize, SMEM_BYTES);

    const int blocks = (LIF_B * LIF_H) / 128;   // 256 blocks, exact cover

    lif_scan_v4b<<<blocks, 32, SMEM_BYTES>>>(x, thr_p, dec_p, out);
}

// round 16
// speedup vs baseline: 1.5105x; 1.0847x over previous
#include <cuda_runtime.h>
#include <cuda_bf16.h>
#include <cstdint>

// LIF spiking scan:  x[B,S,H] -> spikes[B,S,H]   (B=8, S=2048, H=4096, fp32)
//   mem = decay*mem + x_t ; ref = max(ref-1,0)
//   spk = (ref==0 && mem>thr) ; mem *= (1-spk) ; ref += 5*spk
//
// Best = R12 (float4 lanes, 256x32, 6-stage cp.async, STG.128): 95.0us.
// R15 bundled (a) next-eligible-time recurrence encoding [issue work 45.6
// -> 40.5us: GOOD] with (b) STAGES=10 [128 outstanding cp.asyncs/thread =
// LDGSTS queue cap -> producer blocks at issue: BAD, net regression].
// R16 = R12 + (a) only: STAGES=6 static smem (64 outstanding/thread),
// distributed STG.128 stores, na-encoded refractory:
//   sp = (i >= na) && (mem > thr); na = sp ? i+5 : na; na -= U per chunk.
//   (spike at t -> ref=5 -> eligible again exactly at t+5.)

#define LIF_B 8
#define LIF_S 2048
#define LIF_H 4096

static constexpr int U = 16;               // timesteps per stage
static constexpr int STAGES = 6;           // 6*16*128*4B = 48KB static smem
static constexpr int NCHUNK = LIF_S / U;   // 128

__global__ __launch_bounds__(32, 2)
void lif_scan_v4na(const float* __restrict__ x,
                   const float* __restrict__ thr_p,
                   const float* __restrict__ dec_p,
                   float* __restrict__ out)
{
    __shared__ float smem[STAGES][U][128];   // per-stage tile: 16 t x 128 neurons

    const int lane = threadIdx.x;            // 0..31
    const int n0   = blockIdx.x * 128;       // first neuron of this block
    const int b     = n0 >> 12;              // n0 / H
    const int hbase = n0 & (LIF_H - 1);      // n0 % H

    const float thr   = __ldg(thr_p);
    const float decay = __ldg(dec_p);

    const float* __restrict__ xbase = x   + b * (LIF_S * LIF_H) + hbase;
    float* __restrict__       obase = out + b * (LIF_S * LIF_H) + hbase + lane * 4;

    // tile row = 128 floats = 512B = one warp-wide cp.async op (16B/lane).
    const float* __restrict__ wsrc = xbase + lane * 4;
    const unsigned smem0 =
        (unsigned)__cvta_generic_to_shared(&smem[0][0][lane * 4]);

    auto issue_chunk = [&](int c) {
        const unsigned sbase = smem0 + (unsigned)(c % STAGES) * (U * 512u);
        const float* src = wsrc + (c * U) * LIF_H;
        #pragma unroll
        for (int j = 0; j < U; ++j) {
            asm volatile("cp.async.cg.shared.global [%0], [%1], 16;\n"
                         :: "r"(sbase + (unsigned)j * 512u),
                            "l"(src + j * LIF_H));
        }
    };

    // Prologue: fill STAGES-2 stages, one commit group each.
    #pragma unroll
    for (int c = 0; c < STAGES - 2; ++c) {
        issue_chunk(c);
        asm volatile("cp.async.commit_group;\n" ::: "memory");
    }

    // 4 independent neuron states: membrane + next-eligible step (chunk-rel).
    float mem0 = 0.f, mem1 = 0.f, mem2 = 0.f, mem3 = 0.f;
    int   na0 = 0, na1 = 0, na2 = 0, na3 = 0;   // eligible when i >= na

    for (int c = 0; c < NCHUNK; ++c) {
        if (c + STAGES - 2 < NCHUNK)
            issue_chunk(c + STAGES - 2);
        // Always commit (empty tail groups keep wait_group<STAGES-2> aligned
        // so chunk c's group is guaranteed complete below).
        asm volatile("cp.async.commit_group;\n" ::: "memory");
        asm volatile("cp.async.wait_group %0;\n" :: "n"(STAGES - 2) : "memory");
        __syncwarp();   // single-warp block: producer == consumer warp

        const int s = c % STAGES;

        float4 v[U];
        #pragma unroll
        for (int i = 0; i < U; ++i)
            v[i] = *reinterpret_cast<const float4*>(&smem[s][i][lane * 4]);

        float* __restrict__ o = obase + (c * U) * LIF_H;
        #pragma unroll
        for (int i = 0; i < U; ++i) {
            float4 spk;

            mem0 = fmaf(decay, mem0, v[i].x);
            {
                const bool sp = (i >= na0) & (mem0 > thr);
                spk.x = sp ? 1.0f : 0.0f;
                mem0  = sp ? 0.0f : mem0;
                na0   = sp ? (i + 5) : na0;
            }
            mem1 = fmaf(decay, mem1, v[i].y);
            {
                const bool sp = (i >= na1) & (mem1 > thr);
                spk.y = sp ? 1.0f : 0.0f;
                mem1  = sp ? 0.0f : mem1;
                na1   = sp ? (i + 5) : na1;
            }
            mem2 = fmaf(decay, mem2, v[i].z);
            {
                const bool sp = (i >= na2) & (mem2 > thr);
                spk.z = sp ? 1.0f : 0.0f;
                mem2  = sp ? 0.0f : mem2;
                na2   = sp ? (i + 5) : na2;
            }
            mem3 = fmaf(decay, mem3, v[i].w);
            {
                const bool sp = (i >= na3) & (mem3 > thr);
                spk.w = sp ? 1.0f : 0.0f;
                mem3  = sp ? 0.0f : mem3;
                na3   = sp ? (i + 5) : na3;
            }

            *reinterpret_cast<float4*>(&o[i * LIF_H]) = spk;   // STG.128
        }

        // Shift next-eligible times into the next chunk's local frame.
        na0 -= U; na1 -= U; na2 -= U; na3 -= U;
    }
}

extern "C" void kernel_launch(void* const* d_in, const int* in_sizes, int n_in,
                              void* d_out, int out_size)
{
    // metadata order: x [B,S,H] f32, membrane_threshold f32, decay_rate f32
    const float* x     = (const float*)d_in[0];
    const float* thr_p = (const float*)d_in[1];
    const float* dec_p = (const float*)d_in[2];
    float* out = (float*)d_out;

    const int blocks = (LIF_B * LIF_H) / 128;   // 256 blocks, exact cover

    lif_scan_v4na<<<blocks, 32>>>(x, thr_p, dec_p, out);
}